// round 16
// baseline (speedup 1.0000x reference)
#include <cuda_runtime.h>

// ---------------- problem constants ----------------
#define N_IMG   512
#define C_CH    3
#define SDIM    224
#define NPATCH  16
#define PS      14
#define INPUT_D 588        // 3*14*14
#define HID     8
#define HEADS   2
#define DH      4
#define SEQ     257
#define MLPD    32
#define DIMOUT  10
#define EPS_LN  1e-5f
#define NG      8          // images per patch-embed block

// scratch: token/state buffer x[n][257][8]
__device__ float g_x[N_IMG * SEQ * HID];

typedef unsigned long long u64;

// ---------------- packed f32x2 helpers ----------------
__device__ __forceinline__ void fma2(u64& d, u64 a, u64 b) {
    asm("fma.rn.f32x2 %0, %1, %2, %0;" : "+l"(d) : "l"(a), "l"(b));
}
__device__ __forceinline__ void mul2(u64& d, u64 a, u64 b) {
    asm("mul.rn.f32x2 %0, %1, %2;" : "=l"(d) : "l"(a), "l"(b));
}
__device__ __forceinline__ u64 add2(u64 a, u64 b) {
    u64 r;
    asm("add.rn.f32x2 %0, %1, %2;" : "=l"(r) : "l"(a), "l"(b));
    return r;
}
__device__ __forceinline__ u64 packdup(float v) {
    u64 r;
    asm("mov.b64 %0, {%1, %1};" : "=l"(r) : "f"(v));
    return r;
}
__device__ __forceinline__ u64 pack2(float lo, float hi) {
    u64 r;
    asm("mov.b64 %0, {%1, %2};" : "=l"(r) : "f"(lo), "f"(hi));
    return r;
}
__device__ __forceinline__ float2 unpack2(u64 v) {
    float2 f;
    asm("mov.b64 {%0, %1}, %2;" : "=f"(f.x), "=f"(f.y) : "l"(v));
    return f;
}
__device__ __forceinline__ float ex2f(float x) {
    float r;
    asm("ex2.approx.f32 %0, %1;" : "=f"(r) : "f"(x));
    return r;
}

// ---------------- cp.async helpers ----------------
__device__ __forceinline__ void cp16(float* s, const float* g) {
    unsigned sa = (unsigned)__cvta_generic_to_shared(s);
    asm volatile("cp.async.cg.shared.global [%0], [%1], 16;" :: "r"(sa), "l"(g));
}
#define CP_COMMIT() asm volatile("cp.async.commit_group;")
#define CP_WAIT0()  asm volatile("cp.async.wait_group 0;")
#define CP_WAIT1()  asm volatile("cp.async.wait_group 1;")

// ======================================================================
// Kernel A v5: 256 threads, k-split mapping.
// grid (16 py, 64 ig). Thread = (kh = tid>>7, dq = (tid>>5)&3,
// s = lane>>2, pg = lane&3); 4 patches/thread as in R10 (weight reuse
// preserved), k-range split kh=0: k 0..3, kh=1: k 4..6.
// 8 warps/SMSP at 4 CTAs/SM (smem 48.0KB).
// ======================================================================
__global__ void __launch_bounds__(256, 4) patch_embed_kernel(
    const float* __restrict__ images, const int* __restrict__ labels,
    const float* __restrict__ Wm, const float* __restrict__ bm,
    const float* __restrict__ cls_table, const float* __restrict__ pe)
{
    __shared__ float wm_s[INPUT_D * HID];      // 18816 B
    __shared__ float xstripe[2][PS * SDIM];    // 25088 B
    __shared__ float sacc[8][128];             // 4096 B

    const int py  = blockIdx.x;
    const int n0  = blockIdx.y * NG;
    const int tid = threadIdx.x;
    const int lane = tid & 31;
    const int dq   = (tid >> 5) & 3;
    const int kh   = tid >> 7;          // k-half: 0 -> k 0..3, 1 -> k 4..6
    const int pg   = lane & 3;
    const int s    = lane >> 2;
    const int kbeg = kh * 4;
    const int kcnt = kh ? 3 : 4;

    {
        const float* src = images + (size_t)n0 * (C_CH * SDIM * SDIM) + py * (PS * SDIM);
        for (int j = tid; j < PS * SDIM / 4; j += 256) cp16(&xstripe[0][j * 4], src + j * 4);
        CP_COMMIT();
    }
    {
        const float4* src = reinterpret_cast<const float4*>(Wm);
        float4*       dst = reinterpret_cast<float4*>(wm_s);
        for (int i = tid; i < INPUT_D * HID / 4; i += 256) dst[i] = src[i];
    }
    if (py == 0 && tid < NG * 8) {
        int img = tid >> 3, e = tid & 7;
        int lab = labels[n0 + img];
        g_x[(size_t)(n0 + img) * SEQ * HID + e] = cls_table[lab * 8 + e] + pe[e];
    }

    // starting (r, q) for this thread's d-walk
    const int dl0 = dq * 56 + s + 8 * kbeg;
    const int r0  = dl0 / PS;
    const int q0  = dl0 - r0 * PS;

    u64 acc[4][4];
#pragma unroll
    for (int j = 0; j < 4; j++)
#pragma unroll
        for (int p2 = 0; p2 < 4; p2++) acc[j][p2] = 0ull;

    for (int ph = 0; ph < NG * C_CH; ph++) {
        __syncthreads();
        if (ph + 1 < NG * C_CH) {
            int img = (ph + 1) / 3, c = (ph + 1) % 3;
            const float* src = images + (size_t)(n0 + img) * (C_CH * SDIM * SDIM)
                                      + c * (SDIM * SDIM) + py * (PS * SDIM);
            float* dst = xstripe[(ph + 1) & 1];
            for (int j = tid; j < PS * SDIM / 4; j += 256) cp16(dst + j * 4, src + j * 4);
            CP_COMMIT();
            CP_WAIT1();
        } else {
            CP_WAIT0();
        }
        __syncthreads();

        {
            const int c = ph % 3;
            const float* xb = xstripe[ph & 1];
            int dl = dl0, r = r0, q = q0;
#pragma unroll
            for (int k = 0; k < 4; k++) {
                if (k < kcnt && dl < 196) {
                    const ulonglong2* w2 =
                        reinterpret_cast<const ulonglong2*>(wm_s + (c * 196 + dl) * 8);
                    ulonglong2 wa = w2[0], wb = w2[1];
                    int base = r * SDIM + q;
#pragma unroll
                    for (int j = 0; j < 4; j++) {
                        u64 xv2 = packdup(xb[base + (pg + 4 * j) * PS]);
                        fma2(acc[j][0], xv2, wa.x);
                        fma2(acc[j][1], xv2, wa.y);
                        fma2(acc[j][2], xv2, wb.x);
                        fma2(acc[j][3], xv2, wb.y);
                    }
                }
                dl += 8; q += 8;
                if (q >= PS) { q -= PS; r++; }
            }
        }

        if (ph % 3 == 2) {
            const int img = ph / 3;
#pragma unroll
            for (int off = 16; off >= 4; off >>= 1)
#pragma unroll
                for (int j = 0; j < 4; j++)
#pragma unroll
                    for (int p2 = 0; p2 < 4; p2++)
                        acc[j][p2] = add2(acc[j][p2],
                                          __shfl_xor_sync(0xffffffffu, acc[j][p2], off));
            if (s == 0) {
#pragma unroll
                for (int j = 0; j < 4; j++) {
                    int p = pg + 4 * j;
#pragma unroll
                    for (int p2 = 0; p2 < 4; p2++) {
                        float2 f = unpack2(acc[j][p2]);
                        sacc[kh * 4 + dq][p * 8 + p2 * 2]     = f.x;
                        sacc[kh * 4 + dq][p * 8 + p2 * 2 + 1] = f.y;
                    }
                }
            }
#pragma unroll
            for (int j = 0; j < 4; j++)
#pragma unroll
                for (int p2 = 0; p2 < 4; p2++) acc[j][p2] = 0ull;
            __syncthreads();
            if (tid < 128) {
                int p = tid >> 3, e = tid & 7;
                float sum = (sacc[0][tid] + sacc[1][tid])
                          + (sacc[2][tid] + sacc[3][tid])
                          + (sacc[4][tid] + sacc[5][tid])
                          + (sacc[6][tid] + sacc[7][tid]);
                int tok = 1 + py * 16 + p;
                g_x[((size_t)(n0 + img) * SEQ + tok) * HID + e] =
                    sum + __ldg(bm + e) + __ldg(pe + tok * 8 + e);
            }
        }
    }
}

// ======================================================================
// Kernel B (R10-exact): 2-layer transformer + head, one block per image.
// k/v pair-AoS across tokens; 2-rows/thread packed attention; exact erff.
// ======================================================================

#define W_LN1G 0
#define W_LN1B 8
#define W_WQ   16
#define W_BQ   48
#define W_WK   56
#define W_BK   88
#define W_WV   96
#define W_BV   128
#define W_LN2G 136
#define W_LN2B 144
#define W_W1   152    /* W1 TRANSPOSED: [j*8 + d] */
#define W_B1   408
#define W_W2   440
#define W_B2   696

#define QSCALE 0.72134752044f   /* 0.5 * log2(e) */
#define NPAIR  130

__device__ __forceinline__ float pair_elem(const float* base, int t, int c) {
    return base[(t >> 1) * 8 + 2 * c + (t & 1)];
}

__device__ __forceinline__ void q_inline(const float* __restrict__ xrow,
                                         const float* __restrict__ ws,
                                         int hh, float* qo)
{
    float x8[8]; float m = 0.f;
#pragma unroll
    for (int e = 0; e < 8; e++) { x8[e] = xrow[e]; m += x8[e]; }
    m *= 0.125f;
    float var = 0.f;
#pragma unroll
    for (int e = 0; e < 8; e++) { float dd = x8[e] - m; var += dd * dd; }
    float inv = rsqrtf(var * 0.125f + EPS_LN);
    float h[4];
#pragma unroll
    for (int e = 0; e < 4; e++) {
        int d = hh * 4 + e;
        h[e] = (x8[d] - m) * inv * ws[W_LN1G + d] + ws[W_LN1B + d];
    }
    const float4* wq4 = reinterpret_cast<const float4*>(ws + W_WQ);
    float4 qv = reinterpret_cast<const float4*>(ws + W_BQ)[hh];
#pragma unroll
    for (int d = 0; d < 4; d++) {
        float hv = h[d];
        float4 wq = wq4[hh * 4 + d];
        qv.x = fmaf(hv, wq.x, qv.x); qv.y = fmaf(hv, wq.y, qv.y);
        qv.z = fmaf(hv, wq.z, qv.z); qv.w = fmaf(hv, wq.w, qv.w);
    }
    qo[0] = qv.x * QSCALE; qo[1] = qv.y * QSCALE;
    qo[2] = qv.z * QSCALE; qo[3] = qv.w * QSCALE;
}

__global__ void __launch_bounds__(256, 4) vit_blocks_kernel(
    const float* __restrict__ ln1_g, const float* __restrict__ ln1_b,
    const float* __restrict__ Wq, const float* __restrict__ bq,
    const float* __restrict__ Wk, const float* __restrict__ bk,
    const float* __restrict__ Wv, const float* __restrict__ bv,
    const float* __restrict__ ln2_g, const float* __restrict__ ln2_b,
    const float* __restrict__ W1, const float* __restrict__ b1,
    const float* __restrict__ W2, const float* __restrict__ b2,
    const float* __restrict__ Wf, const float* __restrict__ bf,
    float* __restrict__ out)
{
    __shared__ float  xs[SEQ * 9];
    __shared__ __align__(16) u64 kd[2][NPAIR][4];
    __shared__ __align__(16) u64 vd[2][NPAIR][4];
    __shared__ __align__(16) float ws[704];
    __shared__ float  red[8][8];

    const int n   = blockIdx.x;
    const int tid = threadIdx.x;

    for (int i = tid; i < SEQ * HID; i += 256)
        xs[(i >> 3) * 9 + (i & 7)] = g_x[(size_t)n * SEQ * HID + i];

    for (int l = 0; l < 2; l++) {
        __syncthreads();
        if (tid < 8) {
            ws[W_LN1G + tid] = ln1_g[l * 8 + tid];
            ws[W_LN1B + tid] = ln1_b[l * 8 + tid];
            ws[W_BQ   + tid] = bq[l * 8 + tid];
            ws[W_BK   + tid] = bk[l * 8 + tid];
            ws[W_BV   + tid] = bv[l * 8 + tid];
            ws[W_LN2G + tid] = ln2_g[l * 8 + tid];
            ws[W_LN2B + tid] = ln2_b[l * 8 + tid];
            ws[W_B2   + tid] = b2[l * 8 + tid];
        }
        if (tid < 32) {
            ws[W_WQ + tid] = Wq[l * 32 + tid];
            ws[W_WK + tid] = Wk[l * 32 + tid];
            ws[W_WV + tid] = Wv[l * 32 + tid];
            ws[W_B1 + tid] = b1[l * 32 + tid];
        }
        ws[W_W1 + tid] = W1[l * 256 + (tid & 7) * 32 + (tid >> 3)];   // transposed
        ws[W_W2 + tid] = W2[l * 256 + tid];
        __syncthreads();

        // ---- LN1 + K/V projection -> pair-AoS SMEM (no q) ----
        {
            const float4* wk4 = reinterpret_cast<const float4*>(ws + W_WK);
            const float4* wv4 = reinterpret_cast<const float4*>(ws + W_WV);
            const float4* bk4 = reinterpret_cast<const float4*>(ws + W_BK);
            const float4* bv4 = reinterpret_cast<const float4*>(ws + W_BV);
            for (int t = tid; t < SEQ; t += 256) {
                float x8[8]; float m = 0.f;
#pragma unroll
                for (int e = 0; e < 8; e++) { x8[e] = xs[t * 9 + e]; m += x8[e]; }
                m *= 0.125f;
                float var = 0.f;
#pragma unroll
                for (int e = 0; e < 8; e++) { float dd = x8[e] - m; var += dd * dd; }
                float inv = rsqrtf(var * 0.125f + EPS_LN);
                float h[8];
#pragma unroll
                for (int e = 0; e < 8; e++)
                    h[e] = (x8[e] - m) * inv * ws[W_LN1G + e] + ws[W_LN1B + e];
#pragma unroll
                for (int hh = 0; hh < 2; hh++) {
                    float4 kv = bk4[hh], vv = bv4[hh];
#pragma unroll
                    for (int d = 0; d < 4; d++) {
                        float hv = h[hh * 4 + d];
                        float4 wk = wk4[hh * 4 + d];
                        float4 wv = wv4[hh * 4 + d];
                        kv.x = fmaf(hv, wk.x, kv.x); kv.y = fmaf(hv, wk.y, kv.y);
                        kv.z = fmaf(hv, wk.z, kv.z); kv.w = fmaf(hv, wk.w, kv.w);
                        vv.x = fmaf(hv, wv.x, vv.x); vv.y = fmaf(hv, wv.y, vv.y);
                        vv.z = fmaf(hv, wv.z, vv.z); vv.w = fmaf(hv, wv.w, vv.w);
                    }
                    float* kslot = reinterpret_cast<float*>(&kd[hh][t >> 1][0]) + (t & 1);
                    kslot[0] = kv.x; kslot[2] = kv.y; kslot[4] = kv.z; kslot[6] = kv.w;
                    float* vslot = reinterpret_cast<float*>(&vd[hh][t >> 1][0]) + (t & 1);
                    vslot[0] = vv.x; vslot[2] = vv.y; vslot[4] = vv.z; vslot[6] = vv.w;
                }
            }
        }
        __syncthreads();

        // ---- attention ----
        if (l == 0) {
            {
                const int hh = tid >> 7;
                const int j  = tid & 127;
                const int s0 = 2 * j, s1 = s0 + 1;
                float q0[4], q1[4];
                q_inline(xs + s0 * 9, ws, hh, q0);
                q_inline(xs + s1 * 9, ws, hh, q1);
                const u64 q0x = packdup(q0[0]), q0y = packdup(q0[1]),
                          q0z = packdup(q0[2]), q0w = packdup(q0[3]);
                const u64 q1x = packdup(q1[0]), q1y = packdup(q1[1]),
                          q1z = packdup(q1[2]), q1w = packdup(q1[3]);
                const ulonglong2* kp2 = reinterpret_cast<const ulonglong2*>(kd[hh]);
                const ulonglong2* vp2 = reinterpret_cast<const ulonglong2*>(vd[hh]);
                u64 o0x = 0, o0y = 0, o0z = 0, o0w = 0, s0acc = 0;
                u64 o1x = 0, o1y = 0, o1z = 0, o1w = 0, s1acc = 0;
#pragma unroll 2
                for (int tp = 0; tp < 128; tp++) {
                    ulonglong2 kxy = kp2[2 * tp], kzw = kp2[2 * tp + 1];
                    u64 d0, d1;
                    mul2(d0, q0x, kxy.x); mul2(d1, q1x, kxy.x);
                    fma2(d0, q0y, kxy.y); fma2(d1, q1y, kxy.y);
                    fma2(d0, q0z, kzw.x); fma2(d1, q1z, kzw.x);
                    fma2(d0, q0w, kzw.y); fma2(d1, q1w, kzw.y);
                    float2 f0 = unpack2(d0), f1 = unpack2(d1);
                    u64 p0 = pack2(ex2f(f0.x), ex2f(f0.y));
                    u64 p1 = pack2(ex2f(f1.x), ex2f(f1.y));
                    ulonglong2 vxy = vp2[2 * tp], vzw = vp2[2 * tp + 1];
                    fma2(o0x, p0, vxy.x); fma2(o0y, p0, vxy.y);
                    fma2(o0z, p0, vzw.x); fma2(o0w, p0, vzw.y);
                    s0acc = add2(s0acc, p0);
                    fma2(o1x, p1, vxy.x); fma2(o1y, p1, vxy.y);
                    fma2(o1z, p1, vzw.x); fma2(o1w, p1, vzw.y);
                    s1acc = add2(s1acc, p1);
                }
                float2 hx, hy, hz, hw, hs;
                const float* kf = reinterpret_cast<const float*>(kd[hh]);
                const float* vf = reinterpret_cast<const float*>(vd[hh]);
                float k256[4], v256[4];
#pragma unroll
                for (int c = 0; c < 4; c++) {
                    k256[c] = pair_elem(kf, 256, c);
                    v256[c] = pair_elem(vf, 256, c);
                }
                {
                    float dt = fmaf(q0[0], k256[0], fmaf(q0[1], k256[1],
                               fmaf(q0[2], k256[2], q0[3] * k256[3])));
                    float pp = ex2f(dt);
                    hx = unpack2(o0x); hy = unpack2(o0y);
                    hz = unpack2(o0z); hw = unpack2(o0w); hs = unpack2(s0acc);
                    float ox = hx.x + hx.y + pp * v256[0];
                    float oy = hy.x + hy.y + pp * v256[1];
                    float oz = hz.x + hz.y + pp * v256[2];
                    float ow = hw.x + hw.y + pp * v256[3];
                    float invs = 1.f / (hs.x + hs.y + pp);
                    float* xr = xs + s0 * 9 + hh * 4;
                    xr[0] += ox * invs; xr[1] += oy * invs;
                    xr[2] += oz * invs; xr[3] += ow * invs;
                }
                {
                    float dt = fmaf(q1[0], k256[0], fmaf(q1[1], k256[1],
                               fmaf(q1[2], k256[2], q1[3] * k256[3])));
                    float pp = ex2f(dt);
                    hx = unpack2(o1x); hy = unpack2(o1y);
                    hz = unpack2(o1z); hw = unpack2(o1w); hs = unpack2(s1acc);
                    float ox = hx.x + hx.y + pp * v256[0];
                    float oy = hy.x + hy.y + pp * v256[1];
                    float oz = hz.x + hz.y + pp * v256[2];
                    float ow = hw.x + hw.y + pp * v256[3];
                    float invs = 1.f / (hs.x + hs.y + pp);
                    float* xr = xs + s1 * 9 + hh * 4;
                    xr[0] += ox * invs; xr[1] += oy * invs;
                    xr[2] += oz * invs; xr[3] += ow * invs;
                }
            }
            {
                const int wid = tid >> 5, lanei = tid & 31;
                if (wid < 2) {
                    const int hh = wid;
                    float qs[4];
                    q_inline(xs + 256 * 9, ws, hh, qs);
                    const float* kf = reinterpret_cast<const float*>(kd[hh]);
                    const float* vf = reinterpret_cast<const float*>(vd[hh]);
                    float ox = 0.f, oy = 0.f, oz = 0.f, ow = 0.f, ssum = 0.f;
                    for (int t = lanei; t < SEQ; t += 32) {
                        float dt = fmaf(qs[0], pair_elem(kf, t, 0),
                                   fmaf(qs[1], pair_elem(kf, t, 1),
                                   fmaf(qs[2], pair_elem(kf, t, 2),
                                        qs[3] * pair_elem(kf, t, 3))));
                        float pp = ex2f(dt);
                        ox = fmaf(pp, pair_elem(vf, t, 0), ox);
                        oy = fmaf(pp, pair_elem(vf, t, 1), oy);
                        oz = fmaf(pp, pair_elem(vf, t, 2), oz);
                        ow = fmaf(pp, pair_elem(vf, t, 3), ow);
                        ssum += pp;
                    }
#pragma unroll
                    for (int off = 16; off >= 1; off >>= 1) {
                        ox += __shfl_xor_sync(0xffffffffu, ox, off);
                        oy += __shfl_xor_sync(0xffffffffu, oy, off);
                        oz += __shfl_xor_sync(0xffffffffu, oz, off);
                        ow += __shfl_xor_sync(0xffffffffu, ow, off);
                        ssum += __shfl_xor_sync(0xffffffffu, ssum, off);
                    }
                    if (lanei == 0) {
                        float invs = 1.f / ssum;
                        float* xr = xs + 256 * 9 + hh * 4;
                        xr[0] += ox * invs; xr[1] += oy * invs;
                        xr[2] += oz * invs; xr[3] += ow * invs;
                    }
                }
            }
        } else {
            const int hh = tid >> 7;
            const int tl = tid & 127;
            float qs[4];
            q_inline(xs, ws, hh, qs);
            const float* kf = reinterpret_cast<const float*>(kd[hh]);
            const float* vf = reinterpret_cast<const float*>(vd[hh]);
            float ox = 0.f, oy = 0.f, oz = 0.f, ow = 0.f, ssum = 0.f;
            for (int t = tl; t < SEQ; t += 128) {
                float dt = fmaf(qs[0], pair_elem(kf, t, 0),
                           fmaf(qs[1], pair_elem(kf, t, 1),
                           fmaf(qs[2], pair_elem(kf, t, 2),
                                qs[3] * pair_elem(kf, t, 3))));
                float pp = ex2f(dt);
                ox = fmaf(pp, pair_elem(vf, t, 0), ox);
                oy = fmaf(pp, pair_elem(vf, t, 1), oy);
                oz = fmaf(pp, pair_elem(vf, t, 2), oz);
                ow = fmaf(pp, pair_elem(vf, t, 3), ow);
                ssum += pp;
            }
#pragma unroll
            for (int off = 16; off >= 1; off >>= 1) {
                ox += __shfl_xor_sync(0xffffffffu, ox, off);
                oy += __shfl_xor_sync(0xffffffffu, oy, off);
                oz += __shfl_xor_sync(0xffffffffu, oz, off);
                ow += __shfl_xor_sync(0xffffffffu, ow, off);
                ssum += __shfl_xor_sync(0xffffffffu, ssum, off);
            }
            int wid = tid >> 5;
            if ((tid & 31) == 0) {
                red[wid][0] = ox; red[wid][1] = oy;
                red[wid][2] = oz; red[wid][3] = ow;
                red[wid][4] = ssum;
            }
            __syncthreads();
            if (tid < 2) {
                float O0 = 0.f, O1 = 0.f, O2 = 0.f, O3 = 0.f, S = 0.f;
#pragma unroll
                for (int w = 0; w < 4; w++) {
                    int r = tid * 4 + w;
                    O0 += red[r][0]; O1 += red[r][1];
                    O2 += red[r][2]; O3 += red[r][3]; S += red[r][4];
                }
                float invs = 1.f / S;
                float* xr = xs + tid * 4;
                xr[0] += O0 * invs; xr[1] += O1 * invs;
                xr[2] += O2 * invs; xr[3] += O3 * invs;
            }
        }
        __syncthreads();

        // ---- LN2 + MLP (exact GELU), W1 transposed, float4 reads ----
        if (l == 0) {
            const float4* w1t = reinterpret_cast<const float4*>(ws + W_W1);
            const float4* w2r = reinterpret_cast<const float4*>(ws + W_W2);
            for (int t = tid; t < SEQ; t += 256) {
                float x8[8]; float m = 0.f;
#pragma unroll
                for (int e = 0; e < 8; e++) { x8[e] = xs[t * 9 + e]; m += x8[e]; }
                m *= 0.125f;
                float var = 0.f;
#pragma unroll
                for (int e = 0; e < 8; e++) { float dd = x8[e] - m; var += dd * dd; }
                float inv = rsqrtf(var * 0.125f + EPS_LN);
                float h[8];
#pragma unroll
                for (int e = 0; e < 8; e++)
                    h[e] = (x8[e] - m) * inv * ws[W_LN2G + e] + ws[W_LN2B + e];
                float o8[8];
#pragma unroll
                for (int e = 0; e < 8; e++) o8[e] = ws[W_B2 + e];
#pragma unroll 4
                for (int j = 0; j < MLPD; j++) {
                    float4 wa = w1t[2 * j], wb = w1t[2 * j + 1];
                    float a = ws[W_B1 + j]
                            + h[0] * wa.x + h[1] * wa.y + h[2] * wa.z + h[3] * wa.w
                            + h[4] * wb.x + h[5] * wb.y + h[6] * wb.z + h[7] * wb.w;
                    float g = 0.5f * a * (1.f + erff(a * 0.70710678118f));
                    float4 ua = w2r[2 * j], ub = w2r[2 * j + 1];
                    o8[0] = fmaf(g, ua.x, o8[0]); o8[1] = fmaf(g, ua.y, o8[1]);
                    o8[2] = fmaf(g, ua.z, o8[2]); o8[3] = fmaf(g, ua.w, o8[3]);
                    o8[4] = fmaf(g, ub.x, o8[4]); o8[5] = fmaf(g, ub.y, o8[5]);
                    o8[6] = fmaf(g, ub.z, o8[6]); o8[7] = fmaf(g, ub.w, o8[7]);
                }
#pragma unroll
                for (int e = 0; e < 8; e++) xs[t * 9 + e] = x8[e] + o8[e];
            }
        } else {
            if (tid < 32) {
                const float4* w1t = reinterpret_cast<const float4*>(ws + W_W1);
                const float4* w2r = reinterpret_cast<const float4*>(ws + W_W2);
                float x8[8]; float m = 0.f;
#pragma unroll
                for (int e = 0; e < 8; e++) { x8[e] = xs[e]; m += x8[e]; }
                m *= 0.125f;
                float var = 0.f;
#pragma unroll
                for (int e = 0; e < 8; e++) { float dd = x8[e] - m; var += dd * dd; }
                float inv = rsqrtf(var * 0.125f + EPS_LN);
                float h[8];
#pragma unroll
                for (int e = 0; e < 8; e++)
                    h[e] = (x8[e] - m) * inv * ws[W_LN2G + e] + ws[W_LN2B + e];
                float4 wa = w1t[2 * tid], wb = w1t[2 * tid + 1];
                float a = ws[W_B1 + tid]
                        + h[0] * wa.x + h[1] * wa.y + h[2] * wa.z + h[3] * wa.w
                        + h[4] * wb.x + h[5] * wb.y + h[6] * wb.z + h[7] * wb.w;
                float g = 0.5f * a * (1.f + erff(a * 0.70710678118f));
                float o8[8];
                float4 ua = w2r[2 * tid], ub = w2r[2 * tid + 1];
                o8[0] = g * ua.x; o8[1] = g * ua.y; o8[2] = g * ua.z; o8[3] = g * ua.w;
                o8[4] = g * ub.x; o8[5] = g * ub.y; o8[6] = g * ub.z; o8[7] = g * ub.w;
#pragma unroll
                for (int off = 16; off >= 1; off >>= 1)
#pragma unroll
                    for (int e = 0; e < 8; e++)
                        o8[e] += __shfl_xor_sync(0xffffffffu, o8[e], off);
                if (tid == 0) {
#pragma unroll
                    for (int e = 0; e < 8; e++)
                        xs[e] = x8[e] + o8[e] + ws[W_B2 + e];
                }
            }
        }
    }
    __syncthreads();

    if (tid < DIMOUT) {
        float a = bf[tid];
#pragma unroll
        for (int e = 0; e < 8; e++) a += xs[e] * Wf[e * DIMOUT + tid];
        out[n * DIMOUT + tid] = a;
    }
}

// ======================================================================
extern "C" void kernel_launch(void* const* d_in, const int* in_sizes, int n_in,
                              void* d_out, int out_size)
{
    const float* images    = (const float*)d_in[0];
    const int*   labels    = (const int*)  d_in[1];
    const float* Wm        = (const float*)d_in[2];
    const float* bm        = (const float*)d_in[3];
    const float* cls_table = (const float*)d_in[4];
    const float* pe        = (const float*)d_in[5];
    const float* ln1_g     = (const float*)d_in[6];
    const float* ln1_b     = (const float*)d_in[7];
    const float* Wq        = (const float*)d_in[8];
    const float* bq        = (const float*)d_in[9];
    const float* Wk        = (const float*)d_in[10];
    const float* bk        = (const float*)d_in[11];
    const float* Wv        = (const float*)d_in[12];
    const float* bv        = (const float*)d_in[13];
    const float* ln2_g     = (const float*)d_in[14];
    const float* ln2_b     = (const float*)d_in[15];
    const float* W1        = (const float*)d_in[16];
    const float* b1        = (const float*)d_in[17];
    const float* W2        = (const float*)d_in[18];
    const float* b2        = (const float*)d_in[19];
    const float* Wf        = (const float*)d_in[20];
    const float* bf        = (const float*)d_in[21];
    float* out = (float*)d_out;

    dim3 gridA(NPATCH, N_IMG / NG);
    patch_embed_kernel<<<gridA, 256>>>(images, labels, Wm, bm, cls_table, pe);

    vit_blocks_kernel<<<N_IMG, 256>>>(ln1_g, ln1_b, Wq, bq, Wk, bk, Wv, bv,
                                      ln2_g, ln2_b, W1, b1, W2, b2, Wf, bf, out);
}

// round 17
// speedup vs baseline: 1.0619x; 1.0619x over previous
#include <cuda_runtime.h>

// ---------------- problem constants ----------------
#define N_IMG   512
#define C_CH    3
#define SDIM    224
#define NPATCH  16
#define PS      14
#define INPUT_D 588        // 3*14*14
#define HID     8
#define HEADS   2
#define DH      4
#define SEQ     257
#define MLPD    32
#define DIMOUT  10
#define EPS_LN  1e-5f
#define NG      8          // images per patch-embed block

// scratch: token/state buffer x[n][257][8]
__device__ float g_x[N_IMG * SEQ * HID];

typedef unsigned long long u64;

// ---------------- packed f32x2 helpers ----------------
__device__ __forceinline__ void fma2(u64& d, u64 a, u64 b) {
    asm("fma.rn.f32x2 %0, %1, %2, %0;" : "+l"(d) : "l"(a), "l"(b));
}
__device__ __forceinline__ void mul2(u64& d, u64 a, u64 b) {
    asm("mul.rn.f32x2 %0, %1, %2;" : "=l"(d) : "l"(a), "l"(b));
}
__device__ __forceinline__ u64 add2(u64 a, u64 b) {
    u64 r;
    asm("add.rn.f32x2 %0, %1, %2;" : "=l"(r) : "l"(a), "l"(b));
    return r;
}
__device__ __forceinline__ u64 packdup(float v) {
    u64 r;
    asm("mov.b64 %0, {%1, %1};" : "=l"(r) : "f"(v));
    return r;
}
__device__ __forceinline__ u64 pack2(float lo, float hi) {
    u64 r;
    asm("mov.b64 %0, {%1, %2};" : "=l"(r) : "f"(lo), "f"(hi));
    return r;
}
__device__ __forceinline__ float2 unpack2(u64 v) {
    float2 f;
    asm("mov.b64 {%0, %1}, %2;" : "=f"(f.x), "=f"(f.y) : "l"(v));
    return f;
}
__device__ __forceinline__ float ex2f(float x) {
    float r;
    asm("ex2.approx.f32 %0, %1;" : "=f"(r) : "f"(x));
    return r;
}

// ---------------- cp.async helpers ----------------
__device__ __forceinline__ void cp16(float* s, const float* g) {
    unsigned sa = (unsigned)__cvta_generic_to_shared(s);
    asm volatile("cp.async.cg.shared.global [%0], [%1], 16;" :: "r"(sa), "l"(g));
}
#define CP_COMMIT() asm volatile("cp.async.commit_group;")
#define CP_WAIT0()  asm volatile("cp.async.wait_group 0;")
#define CP_WAIT1()  asm volatile("cp.async.wait_group 1;")

// ======================================================================
// Kernel A (R10-exact): patchify + linear proj + pe + cls.
// grid (16 py, 64 ig) x 128 thr. NG=8 imgs/block, double-buffered stripes.
// ======================================================================
__global__ void __launch_bounds__(128) patch_embed_kernel(
    const float* __restrict__ images, const int* __restrict__ labels,
    const float* __restrict__ Wm, const float* __restrict__ bm,
    const float* __restrict__ cls_table, const float* __restrict__ pe)
{
    __shared__ float wm_s[INPUT_D * HID];      // 18816 B
    __shared__ float xstripe[2][PS * SDIM];    // 2 x 12544 B
    __shared__ float sacc[4][16 * 9];          // 2304 B

    const int py  = blockIdx.x;
    const int n0  = blockIdx.y * NG;
    const int tid = threadIdx.x;
    const int lane = tid & 31;
    const int dq   = tid >> 5;
    const int pg   = lane & 3;
    const int s    = lane >> 2;

    {
        const float* src = images + (size_t)n0 * (C_CH * SDIM * SDIM) + py * (PS * SDIM);
        for (int j = tid; j < PS * SDIM / 4; j += 128) cp16(&xstripe[0][j * 4], src + j * 4);
        CP_COMMIT();
    }
    {
        const float4* src = reinterpret_cast<const float4*>(Wm);
        float4*       dst = reinterpret_cast<float4*>(wm_s);
        for (int i = tid; i < INPUT_D * HID / 4; i += 128) dst[i] = src[i];
    }
    if (py == 0 && tid < NG * 8) {
        int img = tid >> 3, e = tid & 7;
        int lab = labels[n0 + img];
        g_x[(size_t)(n0 + img) * SEQ * HID + e] = cls_table[lab * 8 + e] + pe[e];
    }

    u64 acc[4][4];
#pragma unroll
    for (int j = 0; j < 4; j++)
#pragma unroll
        for (int p2 = 0; p2 < 4; p2++) acc[j][p2] = 0ull;

    for (int ph = 0; ph < NG * C_CH; ph++) {
        __syncthreads();
        if (ph + 1 < NG * C_CH) {
            int img = (ph + 1) / 3, c = (ph + 1) % 3;
            const float* src = images + (size_t)(n0 + img) * (C_CH * SDIM * SDIM)
                                      + c * (SDIM * SDIM) + py * (PS * SDIM);
            float* dst = xstripe[(ph + 1) & 1];
            for (int j = tid; j < PS * SDIM / 4; j += 128) cp16(dst + j * 4, src + j * 4);
            CP_COMMIT();
            CP_WAIT1();
        } else {
            CP_WAIT0();
        }
        __syncthreads();

        {
            const int c = ph % 3;
            const float* xb = xstripe[ph & 1];
            int dl = dq * 56 + s;
            int r  = dl / PS;
            int q  = dl - r * PS;
#pragma unroll
            for (int k = 0; k < 7; k++) {
                if (dl < 196) {
                    const ulonglong2* w2 =
                        reinterpret_cast<const ulonglong2*>(wm_s + (c * 196 + dl) * 8);
                    ulonglong2 wa = w2[0], wb = w2[1];
                    int base = r * SDIM + q;
#pragma unroll
                    for (int j = 0; j < 4; j++) {
                        u64 xv2 = packdup(xb[base + (pg + 4 * j) * PS]);
                        fma2(acc[j][0], xv2, wa.x);
                        fma2(acc[j][1], xv2, wa.y);
                        fma2(acc[j][2], xv2, wb.x);
                        fma2(acc[j][3], xv2, wb.y);
                    }
                }
                dl += 8; q += 8;
                if (q >= PS) { q -= PS; r++; }
            }
        }

        if (ph % 3 == 2) {
            const int img = ph / 3;
#pragma unroll
            for (int off = 16; off >= 4; off >>= 1)
#pragma unroll
                for (int j = 0; j < 4; j++)
#pragma unroll
                    for (int p2 = 0; p2 < 4; p2++)
                        acc[j][p2] = add2(acc[j][p2],
                                          __shfl_xor_sync(0xffffffffu, acc[j][p2], off));
            if (s == 0) {
#pragma unroll
                for (int j = 0; j < 4; j++) {
                    int p = pg + 4 * j;
#pragma unroll
                    for (int p2 = 0; p2 < 4; p2++) {
                        float2 f = unpack2(acc[j][p2]);
                        sacc[dq][p * 9 + p2 * 2]     = f.x;
                        sacc[dq][p * 9 + p2 * 2 + 1] = f.y;
                    }
                }
            }
#pragma unroll
            for (int j = 0; j < 4; j++)
#pragma unroll
                for (int p2 = 0; p2 < 4; p2++) acc[j][p2] = 0ull;
            __syncthreads();
            {
                int p = tid >> 3, e = tid & 7;
                float sum = sacc[0][p * 9 + e] + sacc[1][p * 9 + e]
                          + sacc[2][p * 9 + e] + sacc[3][p * 9 + e];
                int tok = 1 + py * 16 + p;
                g_x[((size_t)(n0 + img) * SEQ + tok) * HID + e] =
                    sum + __ldg(bm + e) + __ldg(pe + tok * 8 + e);
            }
        }
    }
}

// ======================================================================
// Kernel B (R10-exact): 2-layer transformer + head, one block per image.
// k/v pair-AoS across tokens; 2-rows/thread packed attention; exact erff.
// ======================================================================

#define W_LN1G 0
#define W_LN1B 8
#define W_WQ   16
#define W_BQ   48
#define W_WK   56
#define W_BK   88
#define W_WV   96
#define W_BV   128
#define W_LN2G 136
#define W_LN2B 144
#define W_W1   152    /* W1 TRANSPOSED: [j*8 + d] */
#define W_B1   408
#define W_W2   440
#define W_B2   696

#define QSCALE 0.72134752044f   /* 0.5 * log2(e) */
#define NPAIR  130

__device__ __forceinline__ float pair_elem(const float* base, int t, int c) {
    return base[(t >> 1) * 8 + 2 * c + (t & 1)];
}

__device__ __forceinline__ void q_inline(const float* __restrict__ xrow,
                                         const float* __restrict__ ws,
                                         int hh, float* qo)
{
    float x8[8]; float m = 0.f;
#pragma unroll
    for (int e = 0; e < 8; e++) { x8[e] = xrow[e]; m += x8[e]; }
    m *= 0.125f;
    float var = 0.f;
#pragma unroll
    for (int e = 0; e < 8; e++) { float dd = x8[e] - m; var += dd * dd; }
    float inv = rsqrtf(var * 0.125f + EPS_LN);
    float h[4];
#pragma unroll
    for (int e = 0; e < 4; e++) {
        int d = hh * 4 + e;
        h[e] = (x8[d] - m) * inv * ws[W_LN1G + d] + ws[W_LN1B + d];
    }
    const float4* wq4 = reinterpret_cast<const float4*>(ws + W_WQ);
    float4 qv = reinterpret_cast<const float4*>(ws + W_BQ)[hh];
#pragma unroll
    for (int d = 0; d < 4; d++) {
        float hv = h[d];
        float4 wq = wq4[hh * 4 + d];
        qv.x = fmaf(hv, wq.x, qv.x); qv.y = fmaf(hv, wq.y, qv.y);
        qv.z = fmaf(hv, wq.z, qv.z); qv.w = fmaf(hv, wq.w, qv.w);
    }
    qo[0] = qv.x * QSCALE; qo[1] = qv.y * QSCALE;
    qo[2] = qv.z * QSCALE; qo[3] = qv.w * QSCALE;
}

__global__ void __launch_bounds__(256, 4) vit_blocks_kernel(
    const float* __restrict__ ln1_g, const float* __restrict__ ln1_b,
    const float* __restrict__ Wq, const float* __restrict__ bq,
    const float* __restrict__ Wk, const float* __restrict__ bk,
    const float* __restrict__ Wv, const float* __restrict__ bv,
    const float* __restrict__ ln2_g, const float* __restrict__ ln2_b,
    const float* __restrict__ W1, const float* __restrict__ b1,
    const float* __restrict__ W2, const float* __restrict__ b2,
    const float* __restrict__ Wf, const float* __restrict__ bf,
    float* __restrict__ out)
{
    __shared__ float  xs[SEQ * 9];
    __shared__ __align__(16) u64 kd[2][NPAIR][4];
    __shared__ __align__(16) u64 vd[2][NPAIR][4];
    __shared__ __align__(16) float ws[704];
    __shared__ float  red[8][8];

    const int n   = blockIdx.x;
    const int tid = threadIdx.x;

    for (int i = tid; i < SEQ * HID; i += 256)
        xs[(i >> 3) * 9 + (i & 7)] = g_x[(size_t)n * SEQ * HID + i];

    for (int l = 0; l < 2; l++) {
        __syncthreads();
        if (tid < 8) {
            ws[W_LN1G + tid] = ln1_g[l * 8 + tid];
            ws[W_LN1B + tid] = ln1_b[l * 8 + tid];
            ws[W_BQ   + tid] = bq[l * 8 + tid];
            ws[W_BK   + tid] = bk[l * 8 + tid];
            ws[W_BV   + tid] = bv[l * 8 + tid];
            ws[W_LN2G + tid] = ln2_g[l * 8 + tid];
            ws[W_LN2B + tid] = ln2_b[l * 8 + tid];
            ws[W_B2   + tid] = b2[l * 8 + tid];
        }
        if (tid < 32) {
            ws[W_WQ + tid] = Wq[l * 32 + tid];
            ws[W_WK + tid] = Wk[l * 32 + tid];
            ws[W_WV + tid] = Wv[l * 32 + tid];
            ws[W_B1 + tid] = b1[l * 32 + tid];
        }
        ws[W_W1 + tid] = W1[l * 256 + (tid & 7) * 32 + (tid >> 3)];   // transposed
        ws[W_W2 + tid] = W2[l * 256 + tid];
        __syncthreads();

        // ---- LN1 + K/V projection -> pair-AoS SMEM (no q) ----
        {
            const float4* wk4 = reinterpret_cast<const float4*>(ws + W_WK);
            const float4* wv4 = reinterpret_cast<const float4*>(ws + W_WV);
            const float4* bk4 = reinterpret_cast<const float4*>(ws + W_BK);
            const float4* bv4 = reinterpret_cast<const float4*>(ws + W_BV);
            for (int t = tid; t < SEQ; t += 256) {
                float x8[8]; float m = 0.f;
#pragma unroll
                for (int e = 0; e < 8; e++) { x8[e] = xs[t * 9 + e]; m += x8[e]; }
                m *= 0.125f;
                float var = 0.f;
#pragma unroll
                for (int e = 0; e < 8; e++) { float dd = x8[e] - m; var += dd * dd; }
                float inv = rsqrtf(var * 0.125f + EPS_LN);
                float h[8];
#pragma unroll
                for (int e = 0; e < 8; e++)
                    h[e] = (x8[e] - m) * inv * ws[W_LN1G + e] + ws[W_LN1B + e];
#pragma unroll
                for (int hh = 0; hh < 2; hh++) {
                    float4 kv = bk4[hh], vv = bv4[hh];
#pragma unroll
                    for (int d = 0; d < 4; d++) {
                        float hv = h[hh * 4 + d];
                        float4 wk = wk4[hh * 4 + d];
                        float4 wv = wv4[hh * 4 + d];
                        kv.x = fmaf(hv, wk.x, kv.x); kv.y = fmaf(hv, wk.y, kv.y);
                        kv.z = fmaf(hv, wk.z, kv.z); kv.w = fmaf(hv, wk.w, kv.w);
                        vv.x = fmaf(hv, wv.x, vv.x); vv.y = fmaf(hv, wv.y, vv.y);
                        vv.z = fmaf(hv, wv.z, vv.z); vv.w = fmaf(hv, wv.w, vv.w);
                    }
                    float* kslot = reinterpret_cast<float*>(&kd[hh][t >> 1][0]) + (t & 1);
                    kslot[0] = kv.x; kslot[2] = kv.y; kslot[4] = kv.z; kslot[6] = kv.w;
                    float* vslot = reinterpret_cast<float*>(&vd[hh][t >> 1][0]) + (t & 1);
                    vslot[0] = vv.x; vslot[2] = vv.y; vslot[4] = vv.z; vslot[6] = vv.w;
                }
            }
        }
        __syncthreads();

        // ---- attention ----
        if (l == 0) {
            {
                const int hh = tid >> 7;
                const int j  = tid & 127;
                const int s0 = 2 * j, s1 = s0 + 1;
                float q0[4], q1[4];
                q_inline(xs + s0 * 9, ws, hh, q0);
                q_inline(xs + s1 * 9, ws, hh, q1);
                const u64 q0x = packdup(q0[0]), q0y = packdup(q0[1]),
                          q0z = packdup(q0[2]), q0w = packdup(q0[3]);
                const u64 q1x = packdup(q1[0]), q1y = packdup(q1[1]),
                          q1z = packdup(q1[2]), q1w = packdup(q1[3]);
                const ulonglong2* kp2 = reinterpret_cast<const ulonglong2*>(kd[hh]);
                const ulonglong2* vp2 = reinterpret_cast<const ulonglong2*>(vd[hh]);
                u64 o0x = 0, o0y = 0, o0z = 0, o0w = 0, s0acc = 0;
                u64 o1x = 0, o1y = 0, o1z = 0, o1w = 0, s1acc = 0;
#pragma unroll 2
                for (int tp = 0; tp < 128; tp++) {
                    ulonglong2 kxy = kp2[2 * tp], kzw = kp2[2 * tp + 1];
                    u64 d0, d1;
                    mul2(d0, q0x, kxy.x); mul2(d1, q1x, kxy.x);
                    fma2(d0, q0y, kxy.y); fma2(d1, q1y, kxy.y);
                    fma2(d0, q0z, kzw.x); fma2(d1, q1z, kzw.x);
                    fma2(d0, q0w, kzw.y); fma2(d1, q1w, kzw.y);
                    float2 f0 = unpack2(d0), f1 = unpack2(d1);
                    u64 p0 = pack2(ex2f(f0.x), ex2f(f0.y));
                    u64 p1 = pack2(ex2f(f1.x), ex2f(f1.y));
                    ulonglong2 vxy = vp2[2 * tp], vzw = vp2[2 * tp + 1];
                    fma2(o0x, p0, vxy.x); fma2(o0y, p0, vxy.y);
                    fma2(o0z, p0, vzw.x); fma2(o0w, p0, vzw.y);
                    s0acc = add2(s0acc, p0);
                    fma2(o1x, p1, vxy.x); fma2(o1y, p1, vxy.y);
                    fma2(o1z, p1, vzw.x); fma2(o1w, p1, vzw.y);
                    s1acc = add2(s1acc, p1);
                }
                float2 hx, hy, hz, hw, hs;
                const float* kf = reinterpret_cast<const float*>(kd[hh]);
                const float* vf = reinterpret_cast<const float*>(vd[hh]);
                float k256[4], v256[4];
#pragma unroll
                for (int c = 0; c < 4; c++) {
                    k256[c] = pair_elem(kf, 256, c);
                    v256[c] = pair_elem(vf, 256, c);
                }
                {
                    float dt = fmaf(q0[0], k256[0], fmaf(q0[1], k256[1],
                               fmaf(q0[2], k256[2], q0[3] * k256[3])));
                    float pp = ex2f(dt);
                    hx = unpack2(o0x); hy = unpack2(o0y);
                    hz = unpack2(o0z); hw = unpack2(o0w); hs = unpack2(s0acc);
                    float ox = hx.x + hx.y + pp * v256[0];
                    float oy = hy.x + hy.y + pp * v256[1];
                    float oz = hz.x + hz.y + pp * v256[2];
                    float ow = hw.x + hw.y + pp * v256[3];
                    float invs = 1.f / (hs.x + hs.y + pp);
                    float* xr = xs + s0 * 9 + hh * 4;
                    xr[0] += ox * invs; xr[1] += oy * invs;
                    xr[2] += oz * invs; xr[3] += ow * invs;
                }
                {
                    float dt = fmaf(q1[0], k256[0], fmaf(q1[1], k256[1],
                               fmaf(q1[2], k256[2], q1[3] * k256[3])));
                    float pp = ex2f(dt);
                    hx = unpack2(o1x); hy = unpack2(o1y);
                    hz = unpack2(o1z); hw = unpack2(o1w); hs = unpack2(s1acc);
                    float ox = hx.x + hx.y + pp * v256[0];
                    float oy = hy.x + hy.y + pp * v256[1];
                    float oz = hz.x + hz.y + pp * v256[2];
                    float ow = hw.x + hw.y + pp * v256[3];
                    float invs = 1.f / (hs.x + hs.y + pp);
                    float* xr = xs + s1 * 9 + hh * 4;
                    xr[0] += ox * invs; xr[1] += oy * invs;
                    xr[2] += oz * invs; xr[3] += ow * invs;
                }
            }
            {
                const int wid = tid >> 5, lanei = tid & 31;
                if (wid < 2) {
                    const int hh = wid;
                    float qs[4];
                    q_inline(xs + 256 * 9, ws, hh, qs);
                    const float* kf = reinterpret_cast<const float*>(kd[hh]);
                    const float* vf = reinterpret_cast<const float*>(vd[hh]);
                    float ox = 0.f, oy = 0.f, oz = 0.f, ow = 0.f, ssum = 0.f;
                    for (int t = lanei; t < SEQ; t += 32) {
                        float dt = fmaf(qs[0], pair_elem(kf, t, 0),
                                   fmaf(qs[1], pair_elem(kf, t, 1),
                                   fmaf(qs[2], pair_elem(kf, t, 2),
                                        qs[3] * pair_elem(kf, t, 3))));
                        float pp = ex2f(dt);
                        ox = fmaf(pp, pair_elem(vf, t, 0), ox);
                        oy = fmaf(pp, pair_elem(vf, t, 1), oy);
                        oz = fmaf(pp, pair_elem(vf, t, 2), oz);
                        ow = fmaf(pp, pair_elem(vf, t, 3), ow);
                        ssum += pp;
                    }
#pragma unroll
                    for (int off = 16; off >= 1; off >>= 1) {
                        ox += __shfl_xor_sync(0xffffffffu, ox, off);
                        oy += __shfl_xor_sync(0xffffffffu, oy, off);
                        oz += __shfl_xor_sync(0xffffffffu, oz, off);
                        ow += __shfl_xor_sync(0xffffffffu, ow, off);
                        ssum += __shfl_xor_sync(0xffffffffu, ssum, off);
                    }
                    if (lanei == 0) {
                        float invs = 1.f / ssum;
                        float* xr = xs + 256 * 9 + hh * 4;
                        xr[0] += ox * invs; xr[1] += oy * invs;
                        xr[2] += oz * invs; xr[3] += ow * invs;
                    }
                }
            }
        } else {
            const int hh = tid >> 7;
            const int tl = tid & 127;
            float qs[4];
            q_inline(xs, ws, hh, qs);
            const float* kf = reinterpret_cast<const float*>(kd[hh]);
            const float* vf = reinterpret_cast<const float*>(vd[hh]);
            float ox = 0.f, oy = 0.f, oz = 0.f, ow = 0.f, ssum = 0.f;
            for (int t = tl; t < SEQ; t += 128) {
                float dt = fmaf(qs[0], pair_elem(kf, t, 0),
                           fmaf(qs[1], pair_elem(kf, t, 1),
                           fmaf(qs[2], pair_elem(kf, t, 2),
                                qs[3] * pair_elem(kf, t, 3))));
                float pp = ex2f(dt);
                ox = fmaf(pp, pair_elem(vf, t, 0), ox);
                oy = fmaf(pp, pair_elem(vf, t, 1), oy);
                oz = fmaf(pp, pair_elem(vf, t, 2), oz);
                ow = fmaf(pp, pair_elem(vf, t, 3), ow);
                ssum += pp;
            }
#pragma unroll
            for (int off = 16; off >= 1; off >>= 1) {
                ox += __shfl_xor_sync(0xffffffffu, ox, off);
                oy += __shfl_xor_sync(0xffffffffu, oy, off);
                oz += __shfl_xor_sync(0xffffffffu, oz, off);
                ow += __shfl_xor_sync(0xffffffffu, ow, off);
                ssum += __shfl_xor_sync(0xffffffffu, ssum, off);
            }
            int wid = tid >> 5;
            if ((tid & 31) == 0) {
                red[wid][0] = ox; red[wid][1] = oy;
                red[wid][2] = oz; red[wid][3] = ow;
                red[wid][4] = ssum;
            }
            __syncthreads();
            if (tid < 2) {
                float O0 = 0.f, O1 = 0.f, O2 = 0.f, O3 = 0.f, S = 0.f;
#pragma unroll
                for (int w = 0; w < 4; w++) {
                    int r = tid * 4 + w;
                    O0 += red[r][0]; O1 += red[r][1];
                    O2 += red[r][2]; O3 += red[r][3]; S += red[r][4];
                }
                float invs = 1.f / S;
                float* xr = xs + tid * 4;
                xr[0] += O0 * invs; xr[1] += O1 * invs;
                xr[2] += O2 * invs; xr[3] += O3 * invs;
            }
        }
        __syncthreads();

        // ---- LN2 + MLP (exact GELU), W1 transposed, float4 reads ----
        if (l == 0) {
            const float4* w1t = reinterpret_cast<const float4*>(ws + W_W1);
            const float4* w2r = reinterpret_cast<const float4*>(ws + W_W2);
            for (int t = tid; t < SEQ; t += 256) {
                float x8[8]; float m = 0.f;
#pragma unroll
                for (int e = 0; e < 8; e++) { x8[e] = xs[t * 9 + e]; m += x8[e]; }
                m *= 0.125f;
                float var = 0.f;
#pragma unroll
                for (int e = 0; e < 8; e++) { float dd = x8[e] - m; var += dd * dd; }
                float inv = rsqrtf(var * 0.125f + EPS_LN);
                float h[8];
#pragma unroll
                for (int e = 0; e < 8; e++)
                    h[e] = (x8[e] - m) * inv * ws[W_LN2G + e] + ws[W_LN2B + e];
                float o8[8];
#pragma unroll
                for (int e = 0; e < 8; e++) o8[e] = ws[W_B2 + e];
#pragma unroll 4
                for (int j = 0; j < MLPD; j++) {
                    float4 wa = w1t[2 * j], wb = w1t[2 * j + 1];
                    float a = ws[W_B1 + j]
                            + h[0] * wa.x + h[1] * wa.y + h[2] * wa.z + h[3] * wa.w
                            + h[4] * wb.x + h[5] * wb.y + h[6] * wb.z + h[7] * wb.w;
                    float g = 0.5f * a * (1.f + erff(a * 0.70710678118f));
                    float4 ua = w2r[2 * j], ub = w2r[2 * j + 1];
                    o8[0] = fmaf(g, ua.x, o8[0]); o8[1] = fmaf(g, ua.y, o8[1]);
                    o8[2] = fmaf(g, ua.z, o8[2]); o8[3] = fmaf(g, ua.w, o8[3]);
                    o8[4] = fmaf(g, ub.x, o8[4]); o8[5] = fmaf(g, ub.y, o8[5]);
                    o8[6] = fmaf(g, ub.z, o8[6]); o8[7] = fmaf(g, ub.w, o8[7]);
                }
#pragma unroll
                for (int e = 0; e < 8; e++) xs[t * 9 + e] = x8[e] + o8[e];
            }
        } else {
            if (tid < 32) {
                const float4* w1t = reinterpret_cast<const float4*>(ws + W_W1);
                const float4* w2r = reinterpret_cast<const float4*>(ws + W_W2);
                float x8[8]; float m = 0.f;
#pragma unroll
                for (int e = 0; e < 8; e++) { x8[e] = xs[e]; m += x8[e]; }
                m *= 0.125f;
                float var = 0.f;
#pragma unroll
                for (int e = 0; e < 8; e++) { float dd = x8[e] - m; var += dd * dd; }
                float inv = rsqrtf(var * 0.125f + EPS_LN);
                float h[8];
#pragma unroll
                for (int e = 0; e < 8; e++)
                    h[e] = (x8[e] - m) * inv * ws[W_LN2G + e] + ws[W_LN2B + e];
                float4 wa = w1t[2 * tid], wb = w1t[2 * tid + 1];
                float a = ws[W_B1 + tid]
                        + h[0] * wa.x + h[1] * wa.y + h[2] * wa.z + h[3] * wa.w
                        + h[4] * wb.x + h[5] * wb.y + h[6] * wb.z + h[7] * wb.w;
                float g = 0.5f * a * (1.f + erff(a * 0.70710678118f));
                float o8[8];
                float4 ua = w2r[2 * tid], ub = w2r[2 * tid + 1];
                o8[0] = g * ua.x; o8[1] = g * ua.y; o8[2] = g * ua.z; o8[3] = g * ua.w;
                o8[4] = g * ub.x; o8[5] = g * ub.y; o8[6] = g * ub.z; o8[7] = g * ub.w;
#pragma unroll
                for (int off = 16; off >= 1; off >>= 1)
#pragma unroll
                    for (int e = 0; e < 8; e++)
                        o8[e] += __shfl_xor_sync(0xffffffffu, o8[e], off);
                if (tid == 0) {
#pragma unroll
                    for (int e = 0; e < 8; e++)
                        xs[e] = x8[e] + o8[e] + ws[W_B2 + e];
                }
            }
        }
    }
    __syncthreads();

    if (tid < DIMOUT) {
        float a = bf[tid];
#pragma unroll
        for (int e = 0; e < 8; e++) a += xs[e] * Wf[e * DIMOUT + tid];
        out[n * DIMOUT + tid] = a;
    }
}

// ======================================================================
extern "C" void kernel_launch(void* const* d_in, const int* in_sizes, int n_in,
                              void* d_out, int out_size)
{
    const float* images    = (const float*)d_in[0];
    const int*   labels    = (const int*)  d_in[1];
    const float* Wm        = (const float*)d_in[2];
    const float* bm        = (const float*)d_in[3];
    const float* cls_table = (const float*)d_in[4];
    const float* pe        = (const float*)d_in[5];
    const float* ln1_g     = (const float*)d_in[6];
    const float* ln1_b     = (const float*)d_in[7];
    const float* Wq        = (const float*)d_in[8];
    const float* bq        = (const float*)d_in[9];
    const float* Wk        = (const float*)d_in[10];
    const float* bk        = (const float*)d_in[11];
    const float* Wv        = (const float*)d_in[12];
    const float* bv        = (const float*)d_in[13];
    const float* ln2_g     = (const float*)d_in[14];
    const float* ln2_b     = (const float*)d_in[15];
    const float* W1        = (const float*)d_in[16];
    const float* b1        = (const float*)d_in[17];
    const float* W2        = (const float*)d_in[18];
    const float* b2        = (const float*)d_in[19];
    const float* Wf        = (const float*)d_in[20];
    const float* bf        = (const float*)d_in[21];
    float* out = (float*)d_out;

    dim3 gridA(NPATCH, N_IMG / NG);
    patch_embed_kernel<<<gridA, 128>>>(images, labels, Wm, bm, cls_table, pe);

    vit_blocks_kernel<<<N_IMG, 256>>>(ln1_g, ln1_b, Wq, bq, Wk, bk, Wv, bv,
                                      ln2_g, ln2_b, W1, b1, W2, b2, Wf, bf, out);
}